// round 3
// baseline (speedup 1.0000x reference)
#include <cuda_runtime.h>
#include <cuda_bf16.h>

// Problem constants
#define BB 8
#define SS 2048
#define FF 256
#define HH 8
#define DD 64
#define PROJ 512            // HH*DD
#define NCHUNK 32           // s-chunks for weighted-sum partials
#define CHUNK 64            // SS/NCHUNK
#define NSC 128             // score stat chunks per (b,h) (16 rows each)

// Scratch (device globals — no allocation allowed)
__device__ float g_p[BB * HH * FF];             // p[b][h][f] = Wk_h @ q_last
__device__ float g_w[BB * HH * SS];             // raw scaled scores
__device__ float g_cm[BB * HH * NSC * 2];       // per-chunk (max, sumexp)
__device__ float g_ms[BB * HH * 2];             // per-(b,h) (max, 1/denom)
__device__ float g_part[BB * NCHUNK * HH * FF]; // partial weighted x sums (8MB)
__device__ float g_attn[BB * PROJ];             // attn concat per batch

// -------------------------------------------------------------------------
// K1: per (b,h): q_h = x[b,S-1,:] @ Wq[:,h*64:+64]; p[b,h,f] = Wk[f,h*64:].q_h
// grid: 64 blocks, 512 threads
// -------------------------------------------------------------------------
__global__ void k_prep(const float* __restrict__ x,
                       const float* __restrict__ Wq,
                       const float* __restrict__ Wk) {
    int blk = blockIdx.x;
    int b = blk >> 3, h = blk & 7;
    int t = threadIdx.x;
    __shared__ float xs[FF];
    __shared__ float qred[8 * DD];
    __shared__ float qs[DD];

    if (t < FF) xs[t] = x[((size_t)b * SS + (SS - 1)) * FF + t];
    __syncthreads();

    {   // q_h[d]: 512 threads = 64 d x 8 f-parts of 32
        int d = t & 63, part = t >> 6;
        const float* wq = Wq + (size_t)(part * 32) * PROJ + h * DD + d;
        const float* xf = xs + part * 32;
        float a = 0.f;
        #pragma unroll
        for (int f = 0; f < 32; ++f) a += xf[f] * wq[(size_t)f * PROJ];
        qred[part * DD + d] = a;
    }
    __syncthreads();
    if (t < DD) {
        float s = 0.f;
        #pragma unroll
        for (int p = 0; p < 8; ++p) s += qred[p * DD + t];
        qs[t] = s;
    }
    __syncthreads();

    int warp = t >> 5, lane = t & 31;
    float q0 = qs[lane], q1 = qs[32 + lane];
    #pragma unroll 4
    for (int i = 0; i < 16; ++i) {
        int f = warp + 16 * i;
        const float* wk = Wk + (size_t)f * PROJ + h * DD;
        float v = wk[lane] * q0 + wk[32 + lane] * q1;
        #pragma unroll
        for (int o = 16; o; o >>= 1) v += __shfl_xor_sync(0xFFFFFFFFu, v, o);
        if (lane == 0) g_p[(b * HH + h) * FF + f] = v;
    }
}

// -------------------------------------------------------------------------
// K2: score[b,h,s] = (x[b,s,:] . p[b,h,:]) / 8 + per-16-row chunk stats
// grid: BB*128 = 1024 blocks (16 rows each), 128 threads (4 warps x 4 rows)
// -------------------------------------------------------------------------
__global__ void k_scores(const float* __restrict__ x) {
    int blk = blockIdx.x;
    int b = blk >> 7;
    int chunk = blk & 127;
    int t = threadIdx.x;
    __shared__ float ps[HH * FF];      // 8KB
    __shared__ float sbuf[HH][16];

    for (int i = t; i < HH * FF; i += 128) ps[i] = g_p[b * HH * FF + i];
    __syncthreads();

    int warp = t >> 5, lane = t & 31;
    const float4* ps4 = (const float4*)ps;

    int s0 = chunk * 16 + warp * 4;
    const float4* xr = (const float4*)(x + ((size_t)b * SS + s0) * FF);

    float4 a[4], c[4];
    #pragma unroll
    for (int r = 0; r < 4; ++r) {
        a[r] = xr[r * 64 + lane];
        c[r] = xr[r * 64 + 32 + lane];
    }

    #pragma unroll
    for (int r = 0; r < 4; ++r) {
        float dot[HH];
        #pragma unroll
        for (int h = 0; h < HH; ++h) {
            float4 pa = ps4[h * 64 + lane];
            float4 pc = ps4[h * 64 + 32 + lane];
            dot[h] = a[r].x * pa.x + a[r].y * pa.y + a[r].z * pa.z + a[r].w * pa.w
                   + c[r].x * pc.x + c[r].y * pc.y + c[r].z * pc.z + c[r].w * pc.w;
        }
        #pragma unroll
        for (int h = 0; h < HH; ++h) {
            #pragma unroll
            for (int o = 16; o; o >>= 1)
                dot[h] += __shfl_xor_sync(0xFFFFFFFFu, dot[h], o);
        }
        if (lane == 0) {
            int s = s0 + r;
            #pragma unroll
            for (int h = 0; h < HH; ++h) {
                float sc = dot[h] * 0.125f;
                g_w[((size_t)(b * HH + h)) * SS + s] = sc;
                sbuf[h][warp * 4 + r] = sc;
            }
        }
    }
    __syncthreads();

    if (t < 8) {
        int h = t;
        float m = -1e30f;
        #pragma unroll
        for (int i = 0; i < 16; ++i) m = fmaxf(m, sbuf[h][i]);
        float s = 0.f;
        #pragma unroll
        for (int i = 0; i < 16; ++i) s += __expf(sbuf[h][i] - m);
        int idx = ((b * HH + h) * NSC + chunk) * 2;
        g_cm[idx] = m;
        g_cm[idx + 1] = s;
    }
}

// -------------------------------------------------------------------------
// K3: reduce chunk stats -> global (max, 1/denom) per (b,h)
// grid: 64 blocks, 128 threads
// -------------------------------------------------------------------------
__global__ void k_stats() {
    int bh = blockIdx.x, t = threadIdx.x;
    float m = g_cm[(bh * NSC + t) * 2];
    float s = g_cm[(bh * NSC + t) * 2 + 1];

    __shared__ float sm[4], ssum[4];
    float M = m;
    #pragma unroll
    for (int o = 16; o; o >>= 1) M = fmaxf(M, __shfl_xor_sync(0xFFFFFFFFu, M, o));
    if ((t & 31) == 0) sm[t >> 5] = M;
    __syncthreads();
    M = fmaxf(fmaxf(sm[0], sm[1]), fmaxf(sm[2], sm[3]));

    float d = s * __expf(m - M);
    #pragma unroll
    for (int o = 16; o; o >>= 1) d += __shfl_xor_sync(0xFFFFFFFFu, d, o);
    if ((t & 31) == 0) ssum[t >> 5] = d;
    __syncthreads();
    if (t == 0) {
        float D = ssum[0] + ssum[1] + ssum[2] + ssum[3];
        g_ms[bh * 2] = M;
        g_ms[bh * 2 + 1] = 1.f / D;
    }
}

// -------------------------------------------------------------------------
// K4: part[b,chunk,h,f] = sum_{s in chunk} softmax_w[b,h,s] * x[b,s,f]
// grid: BB*NCHUNK = 256 blocks, 512 threads
// thread: f4 = t&63 (float4 lane), sg = t>>6 (8 groups x 8 s)
// -------------------------------------------------------------------------
__global__ void k_wsum(const float* __restrict__ x) {
    int blk = blockIdx.x;
    int b = blk >> 5;
    int chunk = blk & 31;
    int t = threadIdx.x;
    __shared__ float ws[HH * CHUNK];    // 2KB
    __shared__ float4 red[4 * 512];     // 32KB

    {   // weights on the fly: one element per thread (512 = HH*CHUNK)
        int h = t >> 6, s = t & 63;
        float m = g_ms[(b * HH + h) * 2];
        float inv = g_ms[(b * HH + h) * 2 + 1];
        float sc = g_w[((size_t)(b * HH + h)) * SS + chunk * CHUNK + s];
        ws[h * CHUNK + s] = __expf(sc - m) * inv;
    }
    __syncthreads();

    int f4 = t & 63, sg = t >> 6;

    float4 acc[HH];
    #pragma unroll
    for (int h = 0; h < HH; ++h) acc[h] = make_float4(0.f, 0.f, 0.f, 0.f);

    const float4* xp = (const float4*)(x + ((size_t)b * SS + chunk * CHUNK) * FF);
    #pragma unroll
    for (int i = 0; i < 8; ++i) {
        int s = sg * 8 + i;
        float4 xv = xp[(size_t)s * 64 + f4];
        #pragma unroll
        for (int h = 0; h < HH; ++h) {
            float w = ws[h * CHUNK + s];
            acc[h].x += w * xv.x; acc[h].y += w * xv.y;
            acc[h].z += w * xv.z; acc[h].w += w * xv.w;
        }
    }

    // staged reduction over sg (8 -> 4 -> 1) within 32KB smem
    if (sg >= 4) {
        #pragma unroll
        for (int h = 0; h < HH; ++h) red[(sg - 4) * 512 + h * 64 + f4] = acc[h];
    }
    __syncthreads();
    if (sg < 4) {
        #pragma unroll
        for (int h = 0; h < HH; ++h) {
            float4 o = red[sg * 512 + h * 64 + f4];
            acc[h].x += o.x; acc[h].y += o.y; acc[h].z += o.z; acc[h].w += o.w;
        }
    }
    __syncthreads();
    if (sg >= 1 && sg < 4) {
        #pragma unroll
        for (int h = 0; h < HH; ++h) red[(sg - 1) * 512 + h * 64 + f4] = acc[h];
    }
    __syncthreads();
    if (sg == 0) {
        float4* out4 = (float4*)(g_part + ((size_t)(b * NCHUNK + chunk)) * (HH * FF));
        #pragma unroll
        for (int h = 0; h < HH; ++h) {
            float4 r = acc[h];
            #pragma unroll
            for (int g = 0; g < 3; ++g) {
                float4 o = red[g * 512 + h * 64 + f4];
                r.x += o.x; r.y += o.y; r.z += o.z; r.w += o.w;
            }
            out4[h * 64 + f4] = r;
        }
    }
}

// -------------------------------------------------------------------------
// K5: per (b,h): y[f] = reduce partials; attn[h*64+d] = sum_f y[f]*Wv[f,h*64+d]
// grid: 64 blocks, 512 threads
// -------------------------------------------------------------------------
__global__ void k_attn(const float* __restrict__ Wv) {
    int blk = blockIdx.x;
    int b = blk >> 3, h = blk & 7;
    int t = threadIdx.x;
    __shared__ float yh2[2][FF];
    __shared__ float ys[FF];
    __shared__ float ared[8 * DD];

    {   // reduce 32 chunks: 512 threads = 256 f x 2 halves of 16 chunks
        int f = t & 255, half = t >> 8;
        const float* pp = g_part + (size_t)b * NCHUNK * (HH * FF) + h * FF + f
                        + (size_t)(half * 16) * (HH * FF);
        float s = 0.f;
        #pragma unroll
        for (int c = 0; c < 16; ++c) s += pp[(size_t)c * (HH * FF)];
        yh2[half][f] = s;
    }
    __syncthreads();
    if (t < FF) ys[t] = yh2[0][t] + yh2[1][t];
    __syncthreads();

    {   // attn: 512 threads = 64 d x 8 f-parts of 32
        int d = t & 63, part = t >> 6;
        const float* wv = Wv + (size_t)(part * 32) * PROJ + h * DD + d;
        const float* yf = ys + part * 32;
        float a = 0.f;
        #pragma unroll
        for (int f = 0; f < 32; ++f) a += yf[f] * wv[(size_t)f * PROJ];
        ared[part * DD + d] = a;
    }
    __syncthreads();
    if (t < DD) {
        float s = 0.f;
        #pragma unroll
        for (int p = 0; p < 8; ++p) s += ared[p * DD + t];
        g_attn[b * PROJ + h * DD + t] = s;
    }
}

// -------------------------------------------------------------------------
// K6: out[b,j] = sum_c attn[b,c] * Wo[c,j] + bo[j]
// grid: 32 blocks (64 j each), 512 threads
// -------------------------------------------------------------------------
__global__ void k_final(const float* __restrict__ Wo,
                        const float* __restrict__ bo,
                        float* __restrict__ out) {
    int blk = blockIdx.x;
    int b = blk >> 2, jblk = blk & 3;
    int t = threadIdx.x;
    __shared__ float as[PROJ];
    __shared__ float ored[8 * 64];

    if (t < PROJ) as[t] = g_attn[b * PROJ + t];
    __syncthreads();

    {
        int j = jblk * 64 + (t & 63);
        int part = t >> 6;   // 8 parts x 64 c
        const float* wo = Wo + (size_t)(part * 64) * FF + j;
        const float* ap = as + part * 64;
        float o = 0.f;
        #pragma unroll
        for (int c = 0; c < 64; ++c) o += ap[c] * wo[(size_t)c * FF];
        ored[part * 64 + (t & 63)] = o;
    }
    __syncthreads();
    if (t < 64) {
        float s = 0.f;
        #pragma unroll
        for (int p = 0; p < 8; ++p) s += ored[p * 64 + t];
        int j = jblk * 64 + t;
        out[b * FF + j] = s + bo[j];
    }
}

// -------------------------------------------------------------------------
extern "C" void kernel_launch(void* const* d_in, const int* in_sizes, int n_in,
                              void* d_out, int out_size) {
    const float* x  = (const float*)d_in[0];
    const float* Wq = (const float*)d_in[1];
    const float* Wk = (const float*)d_in[2];
    const float* Wv = (const float*)d_in[3];
    const float* Wo = (const float*)d_in[4];
    const float* bo = (const float*)d_in[5];
    float* out = (float*)d_out;

    k_prep<<<BB * HH, 512>>>(x, Wq, Wk);
    k_scores<<<BB * NSC, 128>>>(x);
    k_stats<<<BB * HH, 128>>>();
    k_wsum<<<BB * NCHUNK, 512>>>(x);
    k_attn<<<BB * HH, 512>>>(Wv);
    k_final<<<BB * 4, 512>>>(Wo, bo, out);
}

// round 4
// speedup vs baseline: 1.1306x; 1.1306x over previous
#include <cuda_runtime.h>
#include <cuda_bf16.h>

// Problem constants
#define BB 8
#define SS 2048
#define FF 256
#define HH 8
#define DD 64
#define PROJ 512            // HH*DD
#define NCHUNK 64           // s-chunks for weighted-sum partials
#define CHUNK 32            // SS/NCHUNK
#define NSC 64              // score stat chunks per (b,h) (32 rows each)

// Scratch (device globals — no allocation allowed)
__device__ float g_p[BB * HH * FF];             // p[b][h][f] = Wk_h @ q_last
__device__ float g_w[BB * HH * SS];             // raw scaled scores
__device__ float g_cm[BB * HH * NSC * 2];       // per-chunk (max, sumexp)
__device__ float g_part[BB * NCHUNK * HH * FF]; // partial weighted x sums (4MB)
__device__ float g_attn[BB * PROJ];             // attn concat per batch

// -------------------------------------------------------------------------
// K1: per (b,h): q_h = x[b,S-1,:] @ Wq[:,h*64:+64]; p[b,h,f] = Wk[f,h*64:].q_h
// grid: 64 blocks, 512 threads
// -------------------------------------------------------------------------
__global__ void k_prep(const float* __restrict__ x,
                       const float* __restrict__ Wq,
                       const float* __restrict__ Wk) {
    int blk = blockIdx.x;
    int b = blk >> 3, h = blk & 7;
    int t = threadIdx.x;
    __shared__ float xs[FF];
    __shared__ float qred[8 * DD];
    __shared__ float qs[DD];

    if (t < FF) xs[t] = x[((size_t)b * SS + (SS - 1)) * FF + t];
    __syncthreads();

    {   // q_h[d]: 512 threads = 64 d x 8 f-parts of 32
        int d = t & 63, part = t >> 6;
        const float* wq = Wq + (size_t)(part * 32) * PROJ + h * DD + d;
        const float* xf = xs + part * 32;
        float a = 0.f;
        #pragma unroll
        for (int f = 0; f < 32; ++f) a += xf[f] * wq[(size_t)f * PROJ];
        qred[part * DD + d] = a;
    }
    __syncthreads();
    if (t < DD) {
        float s = 0.f;
        #pragma unroll
        for (int p = 0; p < 8; ++p) s += qred[p * DD + t];
        qs[t] = s;
    }
    __syncthreads();

    int warp = t >> 5, lane = t & 31;
    float q0 = qs[lane], q1 = qs[32 + lane];
    #pragma unroll 4
    for (int i = 0; i < 16; ++i) {
        int f = warp + 16 * i;
        const float* wk = Wk + (size_t)f * PROJ + h * DD;
        float v = wk[lane] * q0 + wk[32 + lane] * q1;
        #pragma unroll
        for (int o = 16; o; o >>= 1) v += __shfl_xor_sync(0xFFFFFFFFu, v, o);
        if (lane == 0) g_p[(b * HH + h) * FF + f] = v;
    }
}

// -------------------------------------------------------------------------
// K2: score[b,h,s] = (x[b,s,:] . p[b,h,:]) / 8 + per-32-row chunk stats
// grid: BB*64 = 512 blocks (32 rows each), 256 threads (8 warps x 4 rows)
// -------------------------------------------------------------------------
__global__ void k_scores(const float* __restrict__ x) {
    int blk = blockIdx.x;
    int b = blk >> 6;
    int chunk = blk & 63;
    int t = threadIdx.x;
    __shared__ float ps[HH * FF];      // 8KB
    __shared__ float sbuf[HH][32];

    for (int i = t; i < HH * FF; i += 256) ps[i] = g_p[b * HH * FF + i];
    __syncthreads();

    int warp = t >> 5, lane = t & 31;
    const float4* ps4 = (const float4*)ps;

    int s0 = chunk * 32 + warp * 4;
    const float4* xr = (const float4*)(x + ((size_t)b * SS + s0) * FF);

    // prefetch: 8 outstanding float4 LDGs
    float4 a[4], c[4];
    #pragma unroll
    for (int r = 0; r < 4; ++r) {
        a[r] = xr[r * 64 + lane];
        c[r] = xr[r * 64 + 32 + lane];
    }

    #pragma unroll
    for (int r = 0; r < 4; ++r) {
        float dot[HH];
        #pragma unroll
        for (int h = 0; h < HH; ++h) {
            float4 pa = ps4[h * 64 + lane];
            float4 pc = ps4[h * 64 + 32 + lane];
            dot[h] = a[r].x * pa.x + a[r].y * pa.y + a[r].z * pa.z + a[r].w * pa.w
                   + c[r].x * pc.x + c[r].y * pc.y + c[r].z * pc.z + c[r].w * pc.w;
        }
        #pragma unroll
        for (int h = 0; h < HH; ++h) {
            #pragma unroll
            for (int o = 16; o; o >>= 1)
                dot[h] += __shfl_xor_sync(0xFFFFFFFFu, dot[h], o);
        }
        if (lane == 0) {
            int s = s0 + r;
            #pragma unroll
            for (int h = 0; h < HH; ++h) {
                float sc = dot[h] * 0.125f;
                g_w[((size_t)(b * HH + h)) * SS + s] = sc;
                sbuf[h][warp * 4 + r] = sc;
            }
        }
    }
    __syncthreads();

    if (t < 8) {
        int h = t;
        float m = -1e30f;
        #pragma unroll
        for (int i = 0; i < 32; ++i) m = fmaxf(m, sbuf[h][i]);
        float s = 0.f;
        #pragma unroll
        for (int i = 0; i < 32; ++i) s += __expf(sbuf[h][i] - m);
        int idx = ((b * HH + h) * NSC + chunk) * 2;
        g_cm[idx] = m;
        g_cm[idx + 1] = s;
    }
}

// -------------------------------------------------------------------------
// K3: part[b,chunk,h,f] = sum_{s in chunk} softmax_w[b,h,s] * x[b,s,f]
// Global softmax stats computed in-block from g_cm (warp-per-head).
// grid: BB*NCHUNK = 512 blocks, 256 threads
// main loop: thread = (head-pair hp = t>>6, f4 = t&63); NO cross-thread
// reduction — each thread owns 2 heads' float4 accumulator for this chunk.
// -------------------------------------------------------------------------
__global__ void k_wsum(const float* __restrict__ x) {
    int blk = blockIdx.x;
    int b = blk >> 6;
    int chunk = blk & 63;
    int t = threadIdx.x;
    int warp = t >> 5, lane = t & 31;
    __shared__ float ms[HH][2];
    __shared__ float ws[HH][CHUNK];     // 1KB

    {   // warp h: global (max, 1/denom) for head h from NSC=64 chunk stats
        int h = warp;
        const float* cm = g_cm + (size_t)(b * HH + h) * NSC * 2;
        float m1 = cm[lane * 2],        s1 = cm[lane * 2 + 1];
        float m2 = cm[(lane + 32) * 2], s2 = cm[(lane + 32) * 2 + 1];
        float M = fmaxf(m1, m2);
        #pragma unroll
        for (int o = 16; o; o >>= 1) M = fmaxf(M, __shfl_xor_sync(0xFFFFFFFFu, M, o));
        float d = s1 * __expf(m1 - M) + s2 * __expf(m2 - M);
        #pragma unroll
        for (int o = 16; o; o >>= 1) d += __shfl_xor_sync(0xFFFFFFFFu, d, o);
        if (lane == 0) { ms[h][0] = M; ms[h][1] = 1.f / d; }
    }
    __syncthreads();

    {   // stage softmax weights: 256 threads = HH * CHUNK
        int h = t >> 5, s = t & 31;
        float sc = g_w[((size_t)(b * HH + h)) * SS + chunk * CHUNK + s];
        ws[h][s] = __expf(sc - ms[h][0]) * ms[h][1];
    }
    __syncthreads();

    int f4 = t & 63, hp = t >> 6;
    int h0 = hp * 2;
    float4 a0 = make_float4(0.f, 0.f, 0.f, 0.f);
    float4 a1 = make_float4(0.f, 0.f, 0.f, 0.f);

    const float4* xp = (const float4*)(x + ((size_t)b * SS + chunk * CHUNK) * FF);
    #pragma unroll 8
    for (int s = 0; s < CHUNK; ++s) {
        float4 xv = xp[(size_t)s * 64 + f4];
        float w0 = ws[h0][s], w1 = ws[h0 + 1][s];
        a0.x += w0 * xv.x; a0.y += w0 * xv.y; a0.z += w0 * xv.z; a0.w += w0 * xv.w;
        a1.x += w1 * xv.x; a1.y += w1 * xv.y; a1.z += w1 * xv.z; a1.w += w1 * xv.w;
    }

    float4* out4 = (float4*)(g_part + ((size_t)(b * NCHUNK + chunk)) * (HH * FF));
    out4[h0 * 64 + f4] = a0;
    out4[(h0 + 1) * 64 + f4] = a1;
}

// -------------------------------------------------------------------------
// K4: per (b,h): y[f] = reduce partials; attn[h*64+d] = sum_f y[f]*Wv[f,h*64+d]
// grid: 64 blocks, 512 threads
// -------------------------------------------------------------------------
__global__ void k_attn(const float* __restrict__ Wv) {
    int blk = blockIdx.x;
    int b = blk >> 3, h = blk & 7;
    int t = threadIdx.x;
    __shared__ float yh2[2][FF];
    __shared__ float ys[FF];
    __shared__ float ared[8 * DD];

    {   // reduce 64 chunks: 512 threads = 256 f x 2 halves of 32 chunks
        int f = t & 255, half = t >> 8;
        const float* pp = g_part + (size_t)b * NCHUNK * (HH * FF) + h * FF + f
                        + (size_t)(half * 32) * (HH * FF);
        float s = 0.f;
        #pragma unroll
        for (int c = 0; c < 32; ++c) s += pp[(size_t)c * (HH * FF)];
        yh2[half][f] = s;
    }
    __syncthreads();
    if (t < FF) ys[t] = yh2[0][t] + yh2[1][t];
    __syncthreads();

    {   // attn: 512 threads = 64 d x 8 f-parts of 32
        int d = t & 63, part = t >> 6;
        const float* wv = Wv + (size_t)(part * 32) * PROJ + h * DD + d;
        const float* yf = ys + part * 32;
        float a = 0.f;
        #pragma unroll
        for (int f = 0; f < 32; ++f) a += yf[f] * wv[(size_t)f * PROJ];
        ared[part * DD + d] = a;
    }
    __syncthreads();
    if (t < DD) {
        float s = 0.f;
        #pragma unroll
        for (int p = 0; p < 8; ++p) s += ared[p * DD + t];
        g_attn[b * PROJ + h * DD + t] = s;
    }
}

// -------------------------------------------------------------------------
// K5: out[b,j] = sum_c attn[b,c] * Wo[c,j] + bo[j]
// grid: 32 blocks (64 j each), 512 threads
// -------------------------------------------------------------------------
__global__ void k_final(const float* __restrict__ Wo,
                        const float* __restrict__ bo,
                        float* __restrict__ out) {
    int blk = blockIdx.x;
    int b = blk >> 2, jblk = blk & 3;
    int t = threadIdx.x;
    __shared__ float as[PROJ];
    __shared__ float ored[8 * 64];

    if (t < PROJ) as[t] = g_attn[b * PROJ + t];
    __syncthreads();

    {
        int j = jblk * 64 + (t & 63);
        int part = t >> 6;   // 8 parts x 64 c
        const float* wo = Wo + (size_t)(part * 64) * FF + j;
        const float* ap = as + part * 64;
        float o = 0.f;
        #pragma unroll
        for (int c = 0; c < 64; ++c) o += ap[c] * wo[(size_t)c * FF];
        ored[part * 64 + (t & 63)] = o;
    }
    __syncthreads();
    if (t < 64) {
        float s = 0.f;
        #pragma unroll
        for (int p = 0; p < 8; ++p) s += ored[p * 64 + t];
        int j = jblk * 64 + t;
        out[b * FF + j] = s + bo[j];
    }
}

// -------------------------------------------------------------------------
extern "C" void kernel_launch(void* const* d_in, const int* in_sizes, int n_in,
                              void* d_out, int out_size) {
    const float* x  = (const float*)d_in[0];
    const float* Wq = (const float*)d_in[1];
    const float* Wk = (const float*)d_in[2];
    const float* Wv = (const float*)d_in[3];
    const float* Wo = (const float*)d_in[4];
    const float* bo = (const float*)d_in[5];
    float* out = (float*)d_out;

    k_prep<<<BB * HH, 512>>>(x, Wq, Wk);
    k_scores<<<BB * NSC, 256>>>(x);
    k_wsum<<<BB * NCHUNK, 256>>>(x);
    k_attn<<<BB * HH, 512>>>(Wv);
    k_final<<<BB * 4, 512>>>(Wo, bo, out);
}